// round 1
// baseline (speedup 1.0000x reference)
#include <cuda_runtime.h>
#include <math.h>

// Problem constants: x is (64, 128, 10000) fp32.
#define BATCH 64
#define CH    128
#define T_LEN 10000
#define TT    128          // time-tile per stats block
#define PITCH 129          // odd pitch -> conflict-free column & row smem access

// Scratch (no allocations allowed): channel-mean per (b,t), per-(b,c) sums, final params.
__device__ float g_m[BATCH * T_LEN];      // mean over channels at each (b,t)  (2.56 MB)
__device__ float g_sum [BATCH * CH];      // sum of y over time
__device__ float g_sum2[BATCH * CH];      // sum of y^2 over time
__device__ float g_mean[BATCH * CH];
__device__ float g_istd[BATCH * CH];

// ---------------------------------------------------------------- kernel 0: zero accumulators
__global__ void eeg_zero_kernel() {
    int i = blockIdx.x * blockDim.x + threadIdx.x;
    if (i < BATCH * CH) { g_sum[i] = 0.f; g_sum2[i] = 0.f; }
}

// ---------------------------------------------------------------- kernel 1: tiled stats
// Block = (b, t-chunk of TT). Loads 128ch x TT tile into smem, computes per-t channel mean,
// then per-channel partial sums of y = x - m and y^2, atomically accumulated.
__global__ __launch_bounds__(256) void eeg_stats_kernel(const float* __restrict__ x) {
    extern __shared__ float s[];
    float* tile = s;                    // CH * PITCH
    float* mrow = s + CH * PITCH;       // TT
    float* part = mrow + TT;            // TT

    const int b   = blockIdx.y;
    const int t0  = blockIdx.x * TT;
    const int tid = threadIdx.x;
    const int tx  = tid & (TT - 1);     // 0..127 (time within tile)
    const int ty  = tid >> 7;           // 0..1
    const int vlen = min(TT, T_LEN - t0);

    const float* xb = x + (size_t)b * CH * T_LEN;

    // Load 128 rows; each iteration two rows are read by 256 threads (coalesced along t).
    #pragma unroll 8
    for (int i = 0; i < CH / 2; ++i) {
        int c = 2 * i + ty;
        float v = (tx < vlen) ? xb[(size_t)c * T_LEN + t0 + tx] : 0.f;
        tile[c * PITCH + tx] = v;
    }
    __syncthreads();

    // Column sums over channels: thread pair (ty=0 / ty=1) each sums 64 channels of column tx.
    {
        float sacc = 0.f;
        const int cbeg = ty * 64;
        #pragma unroll 16
        for (int c = 0; c < 64; ++c) sacc += tile[(cbeg + c) * PITCH + tx];
        if (ty == 1) part[tx] = sacc;
        __syncthreads();
        if (ty == 0) {
            float m = (sacc + part[tx]) * (1.0f / 128.0f);
            mrow[tx] = m;
            if (tx < vlen) g_m[(size_t)b * T_LEN + t0 + tx] = m;
        }
    }
    __syncthreads();

    // Per-channel accumulation of y and y^2. Thread (c, half) covers 64 time steps.
    {
        const int c  = tid & (CH - 1);
        const int h  = tid >> 7;
        const int tb = h * 64;
        const int te = min(tb + 64, vlen);
        float sy = 0.f, sy2 = 0.f;
        for (int t = tb; t < te; ++t) {
            float v = tile[c * PITCH + t] - mrow[t];   // mrow[t] is a broadcast read
            sy  += v;
            sy2 += v * v;
        }
        if (te > tb) {
            atomicAdd(&g_sum [b * CH + c], sy);
            atomicAdd(&g_sum2[b * CH + c], sy2);
        }
    }
}

// ---------------------------------------------------------------- kernel 2: finalize mean / inv_std
__global__ void eeg_finalize_kernel() {
    int i = blockIdx.x * blockDim.x + threadIdx.x;
    if (i < BATCH * CH) {
        const float inv_t = 1.0f / (float)T_LEN;
        float mean = g_sum[i] * inv_t;
        float var  = g_sum2[i] * inv_t - mean * mean;
        float sd   = sqrtf(fmaxf(var, 0.f));
        g_mean[i] = mean;
        g_istd[i] = (sd == 0.f) ? 1.f : (1.f / sd);
    }
}

// ---------------------------------------------------------------- kernel 3: normalize (float4)
__global__ __launch_bounds__(256) void eeg_norm_kernel(const float4* __restrict__ x4,
                                                       float4* __restrict__ o4) {
    const int T4 = T_LEN / 4;                    // 2500
    int idx = blockIdx.x * blockDim.x + threadIdx.x;
    if (idx >= BATCH * CH * T4) return;

    int bc = idx / T4;
    int t4 = idx - bc * T4;
    int b  = bc >> 7;                            // bc / 128

    float mean = __ldg(&g_mean[bc]);
    float istd = __ldg(&g_istd[bc]);
    const float4 m4 = *reinterpret_cast<const float4*>(&g_m[(size_t)b * T_LEN + 4 * t4]);
    float4 v = x4[idx];

    float4 r;
    r.x = (v.x - m4.x - mean) * istd;
    r.y = (v.y - m4.y - mean) * istd;
    r.z = (v.z - m4.z - mean) * istd;
    r.w = (v.w - m4.w - mean) * istd;
    o4[idx] = r;
}

// ---------------------------------------------------------------- launch
extern "C" void kernel_launch(void* const* d_in, const int* in_sizes, int n_in,
                              void* d_out, int out_size) {
    (void)in_sizes; (void)n_in; (void)out_size;
    const float* x = (const float*)d_in[0];
    float* out = (float*)d_out;

    // stats kernel needs > 48KB dynamic smem
    static const size_t smem_bytes = (CH * PITCH + 2 * TT) * sizeof(float);  // ~67 KB
    cudaFuncSetAttribute(eeg_stats_kernel,
                         cudaFuncAttributeMaxDynamicSharedMemorySize,
                         (int)smem_bytes);

    // 0) zero accumulators (graph-replay safe)
    eeg_zero_kernel<<<(BATCH * CH + 255) / 256, 256>>>();

    // 1) tiled stats
    dim3 sgrid((T_LEN + TT - 1) / TT, BATCH);    // (79, 64)
    eeg_stats_kernel<<<sgrid, 256, smem_bytes>>>(x);

    // 2) finalize
    eeg_finalize_kernel<<<(BATCH * CH + 255) / 256, 256>>>();

    // 3) normalize
    const int n4 = BATCH * CH * (T_LEN / 4);
    eeg_norm_kernel<<<(n4 + 255) / 256, 256>>>((const float4*)x, (float4*)out);
}

// round 2
// speedup vs baseline: 1.2317x; 1.2317x over previous
#include <cuda_runtime.h>
#include <math.h>

// Problem constants: x is (64, 128, 10000) fp32.
#define BATCH 64
#define CH    128
#define T_LEN 10000
#define TT    128          // time-tile per stats block
#define PITCH 129          // odd pitch -> conflict-free row & column smem access
#define T4    (T_LEN / 4)  // 2500

// Scratch (no allocations allowed).
__device__ float g_m[BATCH * T_LEN];      // mean over channels at each (b,t)  (2.56 MB)
__device__ float g_sum [BATCH * CH];      // sum of y over time
__device__ float g_sum2[BATCH * CH];      // sum of y^2 over time
__device__ float g_mean[BATCH * CH];
__device__ float g_istd[BATCH * CH];

// ---------------------------------------------------------------- kernel 0: zero accumulators
__global__ void eeg_zero_kernel() {
    int i = blockIdx.x * blockDim.x + threadIdx.x;
    if (i < BATCH * CH) { g_sum[i] = 0.f; g_sum2[i] = 0.f; }
}

// ---------------------------------------------------------------- kernel 1: tiled stats
// Block = (b, t-chunk of TT), 256 threads = 8 warps.
// Warp (i,j): t-slice i (32 t), channel-half j (64 ch). While streaming x into the
// smem tile it register-accumulates the per-t channel sum (no smem column pass).
__global__ __launch_bounds__(256) void eeg_stats_kernel(const float* __restrict__ x) {
    extern __shared__ float s[];
    float* tile = s;                    // CH * PITCH
    float* mrow = s + CH * PITCH;       // TT  (channel mean per t)
    float* part = mrow + TT;            // TT  (partial colsum from half j=1)

    const int b    = blockIdx.y;
    const int t0   = blockIdx.x * TT;
    const int tid  = threadIdx.x;
    const int lane = tid & 31;
    const int i    = (tid >> 5) & 3;    // t-slice 0..3
    const int j    = tid >> 7;          // channel half 0..1
    const int tx   = i * 32 + lane;     // 0..127 time within tile
    const int vlen = min(TT, T_LEN - t0);
    const bool valid = tx < vlen;

    const float* __restrict__ xp =
        x + (size_t)b * CH * T_LEN + (size_t)(j * 64) * T_LEN + t0 + tx;
    float* tp = tile + (j * 64) * PITCH + tx;

    // Phase 1: stream 64 channel rows; store tile + register colsum.
    float csum = 0.f;
    #pragma unroll 8
    for (int c = 0; c < 64; ++c) {
        float v = valid ? __ldg(xp + (size_t)c * T_LEN) : 0.f;
        tp[c * PITCH] = v;
        csum += v;
    }
    if (j == 1) part[tx] = csum;
    __syncthreads();

    // Combine halves -> channel mean m[t]; write g_m.
    if (j == 0) {
        float m = (csum + part[tx]) * (1.0f / 128.0f);
        mrow[tx] = m;
        if (valid) g_m[(size_t)b * T_LEN + t0 + tx] = m;
    }
    __syncthreads();

    // Phase 2: per-channel accumulation of y = x - m and y^2 over this t-chunk.
    {
        const int c  = tid & (CH - 1);
        const int h  = tid >> 7;
        const int tb = h * 64;
        const int te = min(tb + 64, vlen);
        float sy = 0.f, sy2 = 0.f;
        const float* trow = tile + c * PITCH;
        #pragma unroll 8
        for (int t = tb; t < te; ++t) {
            float v = trow[t] - mrow[t];       // mrow[t]: broadcast read
            sy  += v;
            sy2 += v * v;
        }
        if (te > tb) {
            atomicAdd(&g_sum [b * CH + c], sy);
            atomicAdd(&g_sum2[b * CH + c], sy2);
        }
    }
}

// ---------------------------------------------------------------- kernel 2: finalize mean / inv_std
__global__ void eeg_finalize_kernel() {
    int i = blockIdx.x * blockDim.x + threadIdx.x;
    if (i < BATCH * CH) {
        const float inv_t = 1.0f / (float)T_LEN;
        float mean = g_sum[i] * inv_t;
        float var  = g_sum2[i] * inv_t - mean * mean;
        float sd   = sqrtf(fmaxf(var, 0.f));
        g_mean[i] = mean;
        g_istd[i] = (sd == 0.f) ? 1.f : (1.f / sd);
    }
}

// ---------------------------------------------------------------- kernel 3: normalize
// grid = (5, 8192): blockIdx.y = (b,c) pair, no integer division. 2 float4 per thread,
// loads front-batched for MLP.
__global__ __launch_bounds__(256) void eeg_norm_kernel(const float4* __restrict__ x4,
                                                       float4* __restrict__ o4) {
    const int bc = blockIdx.y;
    const int b  = bc >> 7;
    const int ta = blockIdx.x * 512 + threadIdx.x;
    const int tb = ta + 256;

    const float mean = g_mean[bc];
    const float istd = g_istd[bc];

    const float4* __restrict__ xp = x4 + (size_t)bc * T4;
    float4*                   op = o4 + (size_t)bc * T4;
    const float4* __restrict__ mp =
        reinterpret_cast<const float4*>(g_m + (size_t)b * T_LEN);  // 40000B rows: 16B aligned

    const bool va = ta < T4;
    const bool vb = tb < T4;

    float4 v0, v1, m0, m1;
    if (va) { v0 = xp[ta]; m0 = mp[ta]; }
    if (vb) { v1 = xp[tb]; m1 = mp[tb]; }

    if (va) {
        float4 r;
        r.x = (v0.x - m0.x - mean) * istd;
        r.y = (v0.y - m0.y - mean) * istd;
        r.z = (v0.z - m0.z - mean) * istd;
        r.w = (v0.w - m0.w - mean) * istd;
        op[ta] = r;
    }
    if (vb) {
        float4 r;
        r.x = (v1.x - m1.x - mean) * istd;
        r.y = (v1.y - m1.y - mean) * istd;
        r.z = (v1.z - m1.z - mean) * istd;
        r.w = (v1.w - m1.w - mean) * istd;
        op[tb] = r;
    }
}

// ---------------------------------------------------------------- launch
extern "C" void kernel_launch(void* const* d_in, const int* in_sizes, int n_in,
                              void* d_out, int out_size) {
    (void)in_sizes; (void)n_in; (void)out_size;
    const float* x = (const float*)d_in[0];
    float* out = (float*)d_out;

    static const size_t smem_bytes = (CH * PITCH + 2 * TT) * sizeof(float);  // ~67 KB
    cudaFuncSetAttribute(eeg_stats_kernel,
                         cudaFuncAttributeMaxDynamicSharedMemorySize,
                         (int)smem_bytes);

    // 0) zero accumulators (graph-replay safe)
    eeg_zero_kernel<<<(BATCH * CH + 255) / 256, 256>>>();

    // 1) tiled stats
    dim3 sgrid((T_LEN + TT - 1) / TT, BATCH);    // (79, 64)
    eeg_stats_kernel<<<sgrid, 256, smem_bytes>>>(x);

    // 2) finalize
    eeg_finalize_kernel<<<(BATCH * CH + 255) / 256, 256>>>();

    // 3) normalize
    dim3 ngrid((T4 + 511) / 512, BATCH * CH);    // (5, 8192)
    eeg_norm_kernel<<<ngrid, 256>>>((const float4*)x, (float4*)out);
}